// round 10
// baseline (speedup 1.0000x reference)
#include <cuda_runtime.h>

// Voronoi nearest-site via fine-grid candidate LUT, L1-resident tables.
// Reference-exact fp32 compare:
//   a  = rn(rn(x0^2) + rn(x1^2))
//   e  = fmaf(x1, sy, rn(x0*sx))
//   d2 = rn(rn(a - 2*e) + cs),  cs = rn(rn(sx^2) + rn(sy^2))
//   argmin: ascending candidate order, strict <  (lowest-index tie-break)
//
// R9 -> R10: keep the winning L1-resident structure (no smem, 8 CTAs/SM,
// streaming ldcs/stcs). Add 2-point vectorized I/O: one float4 ldcs loads 2
// points (halves x-load instrs); 3x float2 stcs per 2 points (store
// wavefronts ~3x down, always 8B aligned); two independent lookup chains
// per iteration hide the ~39cyc L1-hit latency.

#define GR 128
#define NS 100
#define NCELL (GR * GR)

__device__ unsigned int g_grid[NCELL];
__device__ float4 g_cand[NS];   // sx, sy, cs, 0
__device__ float4 g_rgb[NS];    // r, g, b, 0

__global__ void build_lut(const float* __restrict__ p) {
    __shared__ float sp[2 * NS];
    for (int i = threadIdx.x; i < 2 * NS; i += blockDim.x) {
        int s = i >> 1;
        sp[i] = p[1 + 5 * s + (i & 1)];
    }
    __syncthreads();

    int cell = blockIdx.x * blockDim.x + threadIdx.x;
    if (cell >= NCELL) return;

    if (cell < NS) {
        float sx = sp[2 * cell], sy = sp[2 * cell + 1];
        float cs = __fadd_rn(__fmul_rn(sx, sx), __fmul_rn(sy, sy));
        g_cand[cell] = make_float4(sx, sy, cs, 0.0f);
        g_rgb[cell]  = make_float4(p[3 + 5 * cell], p[4 + 5 * cell], p[5 + 5 * cell], 0.0f);
    }

    int gy = cell >> 7;
    int gx = cell & (GR - 1);
    float cx = (gx + 0.5f) * (1.0f / GR);
    float cy = (gy + 0.5f) * (1.0f / GR);

    // 5x5 coarse window: contains the nearest site (d <= 0.1415) and the
    // whole candidate band (reach < 0.2).
    int ci = (int)(cx * 10.0f), cj = (int)(cy * 10.0f);
    int i0 = max(0, ci - 2), i1 = min(9, ci + 2);
    int j0 = max(0, cj - 2), j1 = min(9, cj + 2);

    // Pass 1: nearest d^2 from cell center over the window.
    float best = 3.4e38f;
    for (int ii = i0; ii <= i1; ii++)
        for (int jj = j0; jj <= j1; jj++) {
            int s = ii * 10 + jj;
            float dx = cx - sp[2 * s];
            float dy = cy - sp[2 * s + 1];
            best = fminf(best, fmaf(dx, dx, dy * dy));
        }

    // Band: d(c,s) < d(c,s*) + 2r + slack. 2r = sqrt(2)/128 = 0.011049;
    // slack 1e-4 covers the reference formula's ~4e-7 d2 noise.
    float thr = sqrtf(best) + 0.0110485f + 1e-4f;
    float thr2 = thr * thr;

    unsigned int entry = 0;
    int cnt = 0;
    for (int ii = i0; ii <= i1; ii++)
        for (int jj = j0; jj <= j1; jj++) {   // ascending site ids
            int s = ii * 10 + jj;
            float dx = cx - sp[2 * s];
            float dy = cy - sp[2 * s + 1];
            float d2 = fmaf(dx, dx, dy * dy);
            if (d2 <= thr2) {
                if (cnt < 4) entry |= ((unsigned int)s) << (8 * cnt);
                cnt++;
            }
        }
    if (cnt > 4) {
        entry = (entry & 0xFFu) | 0x0000FE00u | 0x00FF0000u | 0xFF000000u; // 5x5 fallback
    } else {
        for (int k = cnt; k < 4; k++) entry |= 0xFFu << (8 * k);
    }
    g_grid[cell] = entry;
}

__device__ __forceinline__ void eval_cand(
    unsigned int c, float px, float py, float a, float& bd, int& bi)
{
    float4 s = __ldg(&g_cand[c]);
    float ee = __fmaf_rn(py, s.y, __fmul_rn(px, s.x));
    float d2 = __fadd_rn(__fsub_rn(a, __fmul_rn(2.0f, ee)), s.z);
    if (d2 < bd) { bd = d2; bi = (int)c; }
}

__device__ __forceinline__ float4 lookup_one(float px, float py)
{
    int cx = (int)(px * (float)GR);   // exact (GR = 2^7), px in [0,1)
    int cy = (int)(py * (float)GR);
    unsigned int e = __ldg(&g_grid[(cy << 7) + cx]);

    int idx = (int)(e & 0xFFu);
    if ((e >> 8) != 0x00FFFFFFu) {
        float a = __fadd_rn(__fmul_rn(px, px), __fmul_rn(py, py));
        float bd = 3.4e38f;
        int bi = 0;
        if (((e >> 8) & 0xFFu) == 0xFEu) {
            // Rare: 5x5 coarse-neighborhood scan (ascending ids).
            int ci = (int)(px * 10.0f);
            int cj = (int)(py * 10.0f);
            int i1 = min(9, ci + 2), j0 = max(0, cj - 2), j1 = min(9, cj + 2);
            for (int ii = max(0, ci - 2); ii <= i1; ii++)
                for (int jj = j0; jj <= j1; jj++)
                    eval_cand((unsigned int)(ii * 10 + jj), px, py, a, bd, bi);
        } else {
            #pragma unroll
            for (int k = 0; k < 4; k++) {
                unsigned int c = (e >> (8 * k)) & 0xFFu;
                if (c == 0xFFu) break;
                eval_cand(c, px, py, a, bd, bi);
            }
        }
        idx = bi;
    }
    return __ldg(&g_rgb[idx]);
}

__global__ void __launch_bounds__(256, 8) voronoi_main(
    const float4* __restrict__ x4, float* __restrict__ out, int n)
{
    int tid = blockIdx.x * blockDim.x + threadIdx.x;
    int stride = gridDim.x * blockDim.x;
    int ngroups = n >> 1;                 // 2 points per group

    float2* out2 = (float2*)out;
    for (int g = tid; g < ngroups; g += stride) {
        float4 pp = __ldcs(&x4[g]);       // points 2g (pp.x,pp.y), 2g+1 (pp.z,pp.w)

        float4 c0 = lookup_one(pp.x, pp.y);
        float4 c1 = lookup_one(pp.z, pp.w);

        // 6 floats at out[6g..6g+5]: 3x float2, 8B aligned for all g.
        __stcs(&out2[3 * g + 0], make_float2(c0.x, c0.y));
        __stcs(&out2[3 * g + 1], make_float2(c0.z, c1.x));
        __stcs(&out2[3 * g + 2], make_float2(c1.y, c1.z));
    }

    // Odd remainder point.
    if ((n & 1) && tid == 0) {
        const float2* x2 = (const float2*)x4;
        float2 pt = __ldcs(&x2[n - 1]);
        float4 c = lookup_one(pt.x, pt.y);
        out[3 * (n - 1) + 0] = c.x;
        out[3 * (n - 1) + 1] = c.y;
        out[3 * (n - 1) + 2] = c.z;
    }
}

extern "C" void kernel_launch(void* const* d_in, const int* in_sizes, int n_in,
                              void* d_out, int out_size) {
    const float4* x = (const float4*)d_in[0];
    const float*  p = (const float*)d_in[1];
    float* out = (float*)d_out;
    int n = in_sizes[0] / 2;

    build_lut<<<(NCELL + 127) / 128, 128>>>(p);
    voronoi_main<<<1184, 256>>>(x, out, n);   // 8 CTAs/SM, one full wave
}

// round 11
// speedup vs baseline: 1.0779x; 1.0779x over previous
#include <cuda_runtime.h>

// Voronoi nearest-site via fine-grid candidate LUT, L1-resident tables.
// Reference-exact fp32 compare:
//   a  = rn(rn(x0^2) + rn(x1^2))
//   e  = fmaf(x1, sy, rn(x0*sx))
//   d2 = rn(rn(a - 2*e) + cs),  cs = rn(rn(sx^2) + rn(sy^2))
//   argmin: ascending candidate order, strict <  (lowest-index tie-break)
//
// R10 -> R11: revert to R9's scalar I/O main kernel (vector I/O was neutral
// on stores -- they're sector-bound -- and raised L2 churn). New:
//  * PDL: voronoi_main launched with programmatic stream serialization and
//    cudaGridDependencySynchronize() before first LUT read -> its launch
//    overlaps build_lut execution (attacks the 4.8us total-main gap).
//  * #pragma unroll 2 on the grid-stride loop: 2 independent lookup chains.

#define GR 128
#define NS 100
#define NCELL (GR * GR)

__device__ unsigned int g_grid[NCELL];
__device__ float4 g_cand[NS];   // sx, sy, cs, 0
__device__ float4 g_rgb[NS];    // r, g, b, 0

__global__ void build_lut(const float* __restrict__ p) {
    __shared__ float sp[2 * NS];
    for (int i = threadIdx.x; i < 2 * NS; i += blockDim.x) {
        int s = i >> 1;
        sp[i] = p[1 + 5 * s + (i & 1)];
    }
    __syncthreads();

    int cell = blockIdx.x * blockDim.x + threadIdx.x;
    if (cell >= NCELL) return;

    if (cell < NS) {
        float sx = sp[2 * cell], sy = sp[2 * cell + 1];
        float cs = __fadd_rn(__fmul_rn(sx, sx), __fmul_rn(sy, sy));
        g_cand[cell] = make_float4(sx, sy, cs, 0.0f);
        g_rgb[cell]  = make_float4(p[3 + 5 * cell], p[4 + 5 * cell], p[5 + 5 * cell], 0.0f);
    }

    int gy = cell >> 7;
    int gx = cell & (GR - 1);
    float cx = (gx + 0.5f) * (1.0f / GR);
    float cy = (gy + 0.5f) * (1.0f / GR);

    // 5x5 coarse window: contains the nearest site (d <= 0.1415) and the
    // whole candidate band (reach < 0.2).
    int ci = (int)(cx * 10.0f), cj = (int)(cy * 10.0f);
    int i0 = max(0, ci - 2), i1 = min(9, ci + 2);
    int j0 = max(0, cj - 2), j1 = min(9, cj + 2);

    float best = 3.4e38f;
    for (int ii = i0; ii <= i1; ii++)
        for (int jj = j0; jj <= j1; jj++) {
            int s = ii * 10 + jj;
            float dx = cx - sp[2 * s];
            float dy = cy - sp[2 * s + 1];
            best = fminf(best, fmaf(dx, dx, dy * dy));
        }

    // Band: d(c,s) < d(c,s*) + 2r + slack. 2r = sqrt(2)/128 = 0.011049;
    // slack 1e-4 covers the reference formula's ~4e-7 d2 noise.
    float thr = sqrtf(best) + 0.0110485f + 1e-4f;
    float thr2 = thr * thr;

    unsigned int entry = 0;
    int cnt = 0;
    for (int ii = i0; ii <= i1; ii++)
        for (int jj = j0; jj <= j1; jj++) {   // ascending site ids
            int s = ii * 10 + jj;
            float dx = cx - sp[2 * s];
            float dy = cy - sp[2 * s + 1];
            float d2 = fmaf(dx, dx, dy * dy);
            if (d2 <= thr2) {
                if (cnt < 4) entry |= ((unsigned int)s) << (8 * cnt);
                cnt++;
            }
        }
    if (cnt > 4) {
        entry = (entry & 0xFFu) | 0x0000FE00u | 0x00FF0000u | 0xFF000000u; // 5x5 fallback
    } else {
        for (int k = cnt; k < 4; k++) entry |= 0xFFu << (8 * k);
    }
    g_grid[cell] = entry;
}

__device__ __forceinline__ void eval_cand(
    unsigned int c, float px, float py, float a, float& bd, int& bi)
{
    float4 s = __ldg(&g_cand[c]);
    float ee = __fmaf_rn(py, s.y, __fmul_rn(px, s.x));
    float d2 = __fadd_rn(__fsub_rn(a, __fmul_rn(2.0f, ee)), s.z);
    if (d2 < bd) { bd = d2; bi = (int)c; }
}

__device__ __forceinline__ float4 lookup_one(float px, float py)
{
    int cx = (int)(px * (float)GR);   // exact (GR = 2^7), px in [0,1)
    int cy = (int)(py * (float)GR);
    unsigned int e = __ldg(&g_grid[(cy << 7) + cx]);

    int idx = (int)(e & 0xFFu);
    if ((e >> 8) != 0x00FFFFFFu) {
        float a = __fadd_rn(__fmul_rn(px, px), __fmul_rn(py, py));
        float bd = 3.4e38f;
        int bi = 0;
        if (((e >> 8) & 0xFFu) == 0xFEu) {
            // Rare: 5x5 coarse-neighborhood scan (ascending ids).
            int ci = (int)(px * 10.0f);
            int cj = (int)(py * 10.0f);
            int i1 = min(9, ci + 2), j0 = max(0, cj - 2), j1 = min(9, cj + 2);
            for (int ii = max(0, ci - 2); ii <= i1; ii++)
                for (int jj = j0; jj <= j1; jj++)
                    eval_cand((unsigned int)(ii * 10 + jj), px, py, a, bd, bi);
        } else {
            #pragma unroll
            for (int k = 0; k < 4; k++) {
                unsigned int c = (e >> (8 * k)) & 0xFFu;
                if (c == 0xFFu) break;
                eval_cand(c, px, py, a, bd, bi);
            }
        }
        idx = bi;
    }
    return __ldg(&g_rgb[idx]);
}

__global__ void __launch_bounds__(256, 8) voronoi_main(
    const float2* __restrict__ x, float* __restrict__ out, int n)
{
#if __CUDA_ARCH__ >= 900
    cudaGridDependencySynchronize();   // PDL: wait for build_lut results
#endif
    int tid = blockIdx.x * blockDim.x + threadIdx.x;
    int stride = gridDim.x * blockDim.x;

    #pragma unroll 2
    for (int i = tid; i < n; i += stride) {
        float2 pt = __ldcs(&x[i]);             // streaming: don't pollute L1
        float4 c = lookup_one(pt.x, pt.y);
        __stcs(&out[3 * i + 0], c.x);          // streaming stores
        __stcs(&out[3 * i + 1], c.y);
        __stcs(&out[3 * i + 2], c.z);
    }
}

extern "C" void kernel_launch(void* const* d_in, const int* in_sizes, int n_in,
                              void* d_out, int out_size) {
    const float2* x = (const float2*)d_in[0];
    const float*  p = (const float*)d_in[1];
    float* out = (float*)d_out;
    int n = in_sizes[0] / 2;

    build_lut<<<64, 256>>>(p);

    // PDL launch: voronoi_main's launch/prologue overlaps build_lut.
    cudaLaunchConfig_t cfg = {};
    cfg.gridDim  = dim3(1184, 1, 1);   // 8 CTAs/SM x 148 SMs = one full wave
    cfg.blockDim = dim3(256, 1, 1);
    cudaLaunchAttribute attrs[1];
    attrs[0].id = cudaLaunchAttributeProgrammaticStreamSerialization;
    attrs[0].val.programmaticStreamSerializationAllowed = 1;
    cfg.attrs = attrs;
    cfg.numAttrs = 1;
    cudaLaunchKernelEx(&cfg, voronoi_main, x, out, n);
}

// round 12
// speedup vs baseline: 1.1592x; 1.0755x over previous
#include <cuda_runtime.h>

// Voronoi nearest-site via fine-grid candidate LUT. Grid LUT lives in L1
// (one hot copy per SM); small cand/rgb tables live in shared memory.
// Reference-exact fp32 compare:
//   a  = rn(rn(x0^2) + rn(x1^2))
//   e  = fmaf(x1, sy, rn(x0*sx))
//   d2 = rn(rn(a - 2*e) + cs),  cs = rn(rn(sx^2) + rn(sy^2))
//   argmin: ascending candidate order, strict <  (lowest-index tie-break)
//
// R11 -> R12: keep PDL (gap 4.8 -> 3.5us, confirmed win); revert the unroll-2
// (hurt: 24.6 -> 25.7us). New: cand/rgb tables (3.2KB) staged to smem --
// divergent rgb gather moves off the L1TEX wavefront queue onto the smem
// crossbar, freeing L1 for the irreducible random grid gather.

#define GR 128
#define NS 100
#define NCELL (GR * GR)

__device__ unsigned int g_grid[NCELL];
__device__ float4 g_cand[NS];   // sx, sy, cs, 0
__device__ float4 g_rgb[NS];    // r, g, b, 0

__global__ void build_lut(const float* __restrict__ p) {
    __shared__ float sp[2 * NS];
    for (int i = threadIdx.x; i < 2 * NS; i += blockDim.x) {
        int s = i >> 1;
        sp[i] = p[1 + 5 * s + (i & 1)];
    }
    __syncthreads();

    int cell = blockIdx.x * blockDim.x + threadIdx.x;
    if (cell >= NCELL) return;

    if (cell < NS) {
        float sx = sp[2 * cell], sy = sp[2 * cell + 1];
        float cs = __fadd_rn(__fmul_rn(sx, sx), __fmul_rn(sy, sy));
        g_cand[cell] = make_float4(sx, sy, cs, 0.0f);
        g_rgb[cell]  = make_float4(p[3 + 5 * cell], p[4 + 5 * cell], p[5 + 5 * cell], 0.0f);
    }

    int gy = cell >> 7;
    int gx = cell & (GR - 1);
    float cx = (gx + 0.5f) * (1.0f / GR);
    float cy = (gy + 0.5f) * (1.0f / GR);

    // 5x5 coarse window: contains the nearest site (d <= 0.1415) and the
    // whole candidate band (reach < 0.2).
    int ci = (int)(cx * 10.0f), cj = (int)(cy * 10.0f);
    int i0 = max(0, ci - 2), i1 = min(9, ci + 2);
    int j0 = max(0, cj - 2), j1 = min(9, cj + 2);

    float best = 3.4e38f;
    for (int ii = i0; ii <= i1; ii++)
        for (int jj = j0; jj <= j1; jj++) {
            int s = ii * 10 + jj;
            float dx = cx - sp[2 * s];
            float dy = cy - sp[2 * s + 1];
            best = fminf(best, fmaf(dx, dx, dy * dy));
        }

    // Band: d(c,s) < d(c,s*) + 2r + slack. 2r = sqrt(2)/128 = 0.011049;
    // slack 1e-4 covers the reference formula's ~4e-7 d2 noise.
    float thr = sqrtf(best) + 0.0110485f + 1e-4f;
    float thr2 = thr * thr;

    unsigned int entry = 0;
    int cnt = 0;
    for (int ii = i0; ii <= i1; ii++)
        for (int jj = j0; jj <= j1; jj++) {   // ascending site ids
            int s = ii * 10 + jj;
            float dx = cx - sp[2 * s];
            float dy = cy - sp[2 * s + 1];
            float d2 = fmaf(dx, dx, dy * dy);
            if (d2 <= thr2) {
                if (cnt < 4) entry |= ((unsigned int)s) << (8 * cnt);
                cnt++;
            }
        }
    if (cnt > 4) {
        entry = (entry & 0xFFu) | 0x0000FE00u | 0x00FF0000u | 0xFF000000u; // 5x5 fallback
    } else {
        for (int k = cnt; k < 4; k++) entry |= 0xFFu << (8 * k);
    }
    g_grid[cell] = entry;
}

__device__ __forceinline__ void eval_cand(
    unsigned int c, float px, float py, float a,
    const float4* __restrict__ scand, float& bd, int& bi)
{
    float4 s = scand[c];
    float ee = __fmaf_rn(py, s.y, __fmul_rn(px, s.x));
    float d2 = __fadd_rn(__fsub_rn(a, __fmul_rn(2.0f, ee)), s.z);
    if (d2 < bd) { bd = d2; bi = (int)c; }
}

__device__ __forceinline__ float4 lookup_one(
    float px, float py,
    const float4* __restrict__ scand,
    const float4* __restrict__ srgb)
{
    int cx = (int)(px * (float)GR);   // exact (GR = 2^7), px in [0,1)
    int cy = (int)(py * (float)GR);
    unsigned int e = __ldg(&g_grid[(cy << 7) + cx]);

    int idx = (int)(e & 0xFFu);
    if ((e >> 8) != 0x00FFFFFFu) {
        float a = __fadd_rn(__fmul_rn(px, px), __fmul_rn(py, py));
        float bd = 3.4e38f;
        int bi = 0;
        if (((e >> 8) & 0xFFu) == 0xFEu) {
            // Rare: 5x5 coarse-neighborhood scan (ascending ids).
            int ci = (int)(px * 10.0f);
            int cj = (int)(py * 10.0f);
            int i1 = min(9, ci + 2), j0 = max(0, cj - 2), j1 = min(9, cj + 2);
            for (int ii = max(0, ci - 2); ii <= i1; ii++)
                for (int jj = j0; jj <= j1; jj++)
                    eval_cand((unsigned int)(ii * 10 + jj), px, py, a, scand, bd, bi);
        } else {
            #pragma unroll
            for (int k = 0; k < 4; k++) {
                unsigned int c = (e >> (8 * k)) & 0xFFu;
                if (c == 0xFFu) break;
                eval_cand(c, px, py, a, scand, bd, bi);
            }
        }
        idx = bi;
    }
    return srgb[idx];
}

__global__ void __launch_bounds__(256, 8) voronoi_main(
    const float2* __restrict__ x, float* __restrict__ out, int n)
{
    __shared__ float4 scand[NS];   // 1600 B
    __shared__ float4 srgb[NS];    // 1600 B

#if __CUDA_ARCH__ >= 900
    cudaGridDependencySynchronize();   // PDL: wait for build_lut results
#endif
    if (threadIdx.x < NS) {
        scand[threadIdx.x] = g_cand[threadIdx.x];
        srgb[threadIdx.x]  = g_rgb[threadIdx.x];
    }
    __syncthreads();

    int tid = blockIdx.x * blockDim.x + threadIdx.x;
    int stride = gridDim.x * blockDim.x;

    for (int i = tid; i < n; i += stride) {
        float2 pt = __ldcs(&x[i]);             // streaming: don't pollute L1
        float4 c = lookup_one(pt.x, pt.y, scand, srgb);
        __stcs(&out[3 * i + 0], c.x);          // streaming stores
        __stcs(&out[3 * i + 1], c.y);
        __stcs(&out[3 * i + 2], c.z);
    }
}

extern "C" void kernel_launch(void* const* d_in, const int* in_sizes, int n_in,
                              void* d_out, int out_size) {
    const float2* x = (const float2*)d_in[0];
    const float*  p = (const float*)d_in[1];
    float* out = (float*)d_out;
    int n = in_sizes[0] / 2;

    build_lut<<<64, 256>>>(p);

    // PDL launch: voronoi_main's launch/prologue overlaps build_lut.
    cudaLaunchConfig_t cfg = {};
    cfg.gridDim  = dim3(1184, 1, 1);   // 8 CTAs/SM x 148 SMs = one full wave
    cfg.blockDim = dim3(256, 1, 1);
    cudaLaunchAttribute attrs[1];
    attrs[0].id = cudaLaunchAttributeProgrammaticStreamSerialization;
    attrs[0].val.programmaticStreamSerializationAllowed = 1;
    cfg.attrs = attrs;
    cfg.numAttrs = 1;
    cudaLaunchKernelEx(&cfg, voronoi_main, x, out, n);
}